// round 16
// baseline (speedup 1.0000x reference)
#include <cuda_runtime.h>
#include <cuda_bf16.h>
#include <cuda_fp16.h>

// FrozenBNBStableEmbedding fused gather+dequant+LayerNorm.
// R16 = R5 champion skeleton VERBATIM (grid=1024, warp-per-token, TPW=2,
// per-token epilogue, MLP=8 front-batched loads, REP=16 table, inline scale,
// LN params from smem, __stcs) with exactly ONE change: the dequantized row
// is held as __half2[16] instead of float[32] (stats computed in f32 before
// packing; fp16 rounding only affects the epilogue input, ~1e-4 rel err,
// gate 1e-3). Saves 16 regs -> ~48 -> launch_bounds(256,5): 5 CTAs/SM,
// occ ~59% vs 42%. Kernel is latency-bound; more warps = more hiding.

#define D    1024
#define REP  16
#define TPW  2
#define EPS  1e-5f

__global__ __launch_bounds__(256, 5) void emb_ln_kernel(
    const int*   __restrict__ x,
    const int*   __restrict__ w,
    const float* __restrict__ absmax,
    const float* __restrict__ code,
    const float* __restrict__ lnw,
    const float* __restrict__ lnb,
    float*       __restrict__ out,
    int n_tokens)
{
    __shared__ float  s_code[256 * REP];  // s_code[idx*REP + slot]
    __shared__ float4 s_lnw[256];
    __shared__ float4 s_lnb[256];

    const int tid  = threadIdx.x;
    const int warp = tid >> 5;
    const int lane = tid & 31;

    // Fill replicated code table + LN params (once per CTA)
    {
        const float c = code[tid];
        float4 cv = make_float4(c, c, c, c);
        float4* dst = reinterpret_cast<float4*>(&s_code[tid * REP]);
        dst[0] = cv; dst[1] = cv; dst[2] = cv; dst[3] = cv;
        s_lnw[tid] = __ldg(&reinterpret_cast<const float4*>(lnw)[tid]);
        s_lnb[tid] = __ldg(&reinterpret_cast<const float4*>(lnb)[tid]);
    }
    __syncthreads();

    const float* tab = &s_code[lane & (REP - 1)];
    const int warp_g = blockIdx.x * 8 + warp;

    #pragma unroll
    for (int t = 0; t < TPW; ++t) {
        const int tok = warp_g * TPW + t;
        if (tok >= n_tokens) break;

        const int   row   = __ldg(&x[tok]);
        const float scale = __ldg(&absmax[row >> 2]);
        const int4* wrow  = reinterpret_cast<const int4*>(w + (long long)row * D);

        // 8 independent 16B loads, front-batched: MLP = 8
        int4 q[8];
        #pragma unroll
        for (int i = 0; i < 8; ++i)
            q[i] = __ldg(&wrow[i * 32 + lane]);

        // Dequant; f32 stats; pack values to half2 (reg pressure: 16 vs 32)
        __half2 vh[16];
        float sum = 0.0f, sq = 0.0f;
        #pragma unroll
        for (int i = 0; i < 8; ++i) {
            float a = tab[(q[i].x & 255) * REP] * scale;
            float b = tab[(q[i].y & 255) * REP] * scale;
            float c = tab[(q[i].z & 255) * REP] * scale;
            float d = tab[(q[i].w & 255) * REP] * scale;
            sum += a + b + c + d;
            sq  += a*a + b*b + c*c + d*d;
            vh[i*2+0] = __floats2half2_rn(a, b);
            vh[i*2+1] = __floats2half2_rn(c, d);
        }

        // Butterfly reduction (sum & sq chains interleave)
        #pragma unroll
        for (int off = 16; off > 0; off >>= 1) {
            sum += __shfl_xor_sync(0xFFFFFFFFu, sum, off);
            sq  += __shfl_xor_sync(0xFFFFFFFFu, sq,  off);
        }
        const float mean = sum * (1.0f / D);
        const float rstd = rsqrtf(sq * (1.0f / D) - mean * mean + EPS);

        float4* orow = reinterpret_cast<float4*>(out) + (long long)tok * (D / 4);
        #pragma unroll
        for (int i = 0; i < 8; ++i) {
            const float4 gw = s_lnw[i * 32 + lane];
            const float4 gb = s_lnb[i * 32 + lane];
            const float2 p0 = __half22float2(vh[i*2+0]);
            const float2 p1 = __half22float2(vh[i*2+1]);
            float4 o;
            o.x = (p0.x - mean) * rstd * gw.x + gb.x;
            o.y = (p0.y - mean) * rstd * gw.y + gb.y;
            o.z = (p1.x - mean) * rstd * gw.z + gb.z;
            o.w = (p1.y - mean) * rstd * gw.w + gb.w;
            __stcs(&orow[i * 32 + lane], o);
        }
    }
}

extern "C" void kernel_launch(void* const* d_in, const int* in_sizes, int n_in,
                              void* d_out, int out_size)
{
    const int*   x      = (const int*)d_in[0];
    const int*   w      = (const int*)d_in[1];
    const float* absmax = (const float*)d_in[2];
    const float* code   = (const float*)d_in[3];
    const float* lnw    = (const float*)d_in[4];
    const float* lnb    = (const float*)d_in[5];
    float*       out    = (float*)d_out;

    const int n_tokens = in_sizes[0];                     // 16384
    const int tokens_per_cta = 8 * TPW;                   // 16
    const int grid = (n_tokens + tokens_per_cta - 1) / tokens_per_cta;  // 1024
    emb_ln_kernel<<<grid, 256>>>(x, w, absmax, code, lnw, lnb, out, n_tokens);
}

// round 17
// speedup vs baseline: 1.1032x; 1.1032x over previous
#include <cuda_runtime.h>
#include <cuda_bf16.h>

// FrozenBNBStableEmbedding fused gather+dequant+LayerNorm.
// R17 = R5 champion, byte-for-byte (reproducibility control after 11
// perturbations all regressed). Warp-per-token, TPW=2, grid=1024,
// MLP=8 front-batched weight loads, REP=16 replicated code table,
// inline scale, LN params from smem, shfl butterfly, __stcs stores.

#define D    1024
#define REP  16          // code-table replication
#define TPW  2           // tokens per warp
#define EPS  1e-5f

__global__ __launch_bounds__(256) void emb_ln_kernel(
    const int*   __restrict__ x,
    const int*   __restrict__ w,
    const float* __restrict__ absmax,
    const float* __restrict__ code,
    const float* __restrict__ lnw,
    const float* __restrict__ lnb,
    float*       __restrict__ out,
    int n_tokens)
{
    __shared__ float  s_code[256 * REP];  // s_code[idx*REP + slot]
    __shared__ float4 s_lnw[256];
    __shared__ float4 s_lnb[256];

    const int tid  = threadIdx.x;
    const int warp = tid >> 5;
    const int lane = tid & 31;

    // Fill replicated code table + LN params (once per CTA)
    {
        const float c = code[tid];
        float4 cv = make_float4(c, c, c, c);
        float4* dst = reinterpret_cast<float4*>(&s_code[tid * REP]);
        dst[0] = cv; dst[1] = cv; dst[2] = cv; dst[3] = cv;
        s_lnw[tid] = __ldg(&reinterpret_cast<const float4*>(lnw)[tid]);
        s_lnb[tid] = __ldg(&reinterpret_cast<const float4*>(lnb)[tid]);
    }
    __syncthreads();

    const float* tab = &s_code[lane & (REP - 1)];
    const int warp_g = blockIdx.x * 8 + warp;

    #pragma unroll
    for (int t = 0; t < TPW; ++t) {
        const int tok = warp_g * TPW + t;
        if (tok >= n_tokens) break;

        const int   row   = __ldg(&x[tok]);
        const float scale = __ldg(&absmax[row >> 2]);
        const int4* wrow  = reinterpret_cast<const int4*>(w + (long long)row * D);

        // 8 independent 16B loads: MLP = 8
        int4 q[8];
        #pragma unroll
        for (int i = 0; i < 8; ++i)
            q[i] = __ldg(&wrow[i * 32 + lane]);

        float v[32];
        float sum = 0.0f, sq = 0.0f;
        #pragma unroll
        for (int i = 0; i < 8; ++i) {
            float a = tab[(q[i].x & 255) * REP] * scale;
            float b = tab[(q[i].y & 255) * REP] * scale;
            float c = tab[(q[i].z & 255) * REP] * scale;
            float d = tab[(q[i].w & 255) * REP] * scale;
            v[i*4+0] = a; v[i*4+1] = b; v[i*4+2] = c; v[i*4+3] = d;
            sum += a + b + c + d;
            sq  += a*a + b*b + c*c + d*d;
        }

        // Warp-level reduction (butterfly leaves total in every lane)
        #pragma unroll
        for (int off = 16; off > 0; off >>= 1) {
            sum += __shfl_xor_sync(0xFFFFFFFFu, sum, off);
            sq  += __shfl_xor_sync(0xFFFFFFFFu, sq,  off);
        }
        const float mean = sum * (1.0f / D);
        const float rstd = rsqrtf(sq * (1.0f / D) - mean * mean + EPS);

        float4* orow = reinterpret_cast<float4*>(out) + (long long)tok * (D / 4);
        #pragma unroll
        for (int i = 0; i < 8; ++i) {
            const float4 gw = s_lnw[i * 32 + lane];
            const float4 gb = s_lnb[i * 32 + lane];
            float4 o;
            o.x = (v[i*4+0] - mean) * rstd * gw.x + gb.x;
            o.y = (v[i*4+1] - mean) * rstd * gw.y + gb.y;
            o.z = (v[i*4+2] - mean) * rstd * gw.z + gb.z;
            o.w = (v[i*4+3] - mean) * rstd * gw.w + gb.w;
            __stcs(&orow[i * 32 + lane], o);
        }
    }
}

extern "C" void kernel_launch(void* const* d_in, const int* in_sizes, int n_in,
                              void* d_out, int out_size)
{
    const int*   x      = (const int*)d_in[0];
    const int*   w      = (const int*)d_in[1];
    const float* absmax = (const float*)d_in[2];
    const float* code   = (const float*)d_in[3];
    const float* lnw    = (const float*)d_in[4];
    const float* lnb    = (const float*)d_in[5];
    float*       out    = (float*)d_out;

    const int n_tokens = in_sizes[0];                     // 16384
    const int tokens_per_cta = 8 * TPW;                   // 16
    const int grid = (n_tokens + tokens_per_cta - 1) / tokens_per_cta;  // 1024
    emb_ln_kernel<<<grid, 256>>>(x, w, absmax, code, lnw, lnb, out, n_tokens);
}